// round 7
// baseline (speedup 1.0000x reference)
#include <cuda_runtime.h>
#include <math.h>
#include <stdint.h>

// Problem constants (fixed by the dataset)
#define NN 40000      // node_size
#define RR 2000       // rel_size
#define TT 600000     // triple_size
#define DD 128        // DIM
#define F3 384        // DIM*(DEPTH+1)
#define NP 64         // num proxies
#define EPS 1e-12f
#define NBLK 40       // ceil(NN/1024)
#define NPAD 40064    // NN padded to 128-row multiple for GEMM tiles

// ----------------------------------------------------------------------------
// Device scratch (static: no allocation allowed; zero-initialized at load)
// ----------------------------------------------------------------------------
__device__ float g_rel_norm[RR * DD];        // normalized rel_emb
__device__ float g_rel_w[4][RR];             // exp(edge-attn logit) per [enc*2+layer][rel]
__device__ float g_pnormT[2][F3 * NP];       // transposed normalized proxies [i*64+p]

__device__ int g_cnt[3][NN];                 // per-row degree (3 adjacencies)
__device__ int g_rowptr[3][NN + 1];
__device__ int g_cur[3][NN];
__device__ int g_bsum[3][NBLK];
__device__ int g_boff[3][NBLK];

__device__ int g_eA_col[TT];                 // ent_adj cols (CSR order)
__device__ int g_eB_col[TT];                 // rel_adj cols (rel ids)
__device__ int g_eC_col[TT];                 // adj_list cols (node ids)
__device__ int g_eC_rel[TT];                 // rel id, or -1 if r_val == 0

__device__ float g_fA[NN * DD];              // ping
__device__ float g_fB[NN * DD];              // pong
__device__ float g_pf[2][(size_t)NPAD * F3]; // proxy-filtered per encoder (pad rows stay 0)
__device__ float g_dummy[(size_t)NN * 768];  // probe sink (never read by real path)

// ----------------------------------------------------------------------------
// Warp helpers
// ----------------------------------------------------------------------------
__device__ __forceinline__ float wsum(float v) {
    #pragma unroll
    for (int o = 16; o; o >>= 1) v += __shfl_xor_sync(0xffffffffu, v, o);
    return v;
}
__device__ __forceinline__ float wmax(float v) {
    #pragma unroll
    for (int o = 16; o; o >>= 1) v = fmaxf(v, __shfl_xor_sync(0xffffffffu, v, o));
    return v;
}

// ----------------------------------------------------------------------------
// Prep: normalized relation embeddings + per-relation attention exp-weights
// ----------------------------------------------------------------------------
__global__ void prep_rel_kernel(const float* __restrict__ rel_emb,
                                const float* __restrict__ e_attn,
                                const float* __restrict__ r_attn) {
    int w = (blockIdx.x * blockDim.x + threadIdx.x) >> 5;
    int lane = threadIdx.x & 31;
    if (w >= RR) return;
    float4 v = ((const float4*)rel_emb)[w * 32 + lane];
    float ss = v.x * v.x + v.y * v.y + v.z * v.z + v.w * v.w;
    ss = wsum(ss);
    float inv = 1.f / fmaxf(sqrtf(ss), EPS);
    float4 nv = make_float4(v.x * inv, v.y * inv, v.z * inv, v.w * inv);
    ((float4*)g_rel_norm)[w * 32 + lane] = nv;
    const float* av[4] = { e_attn, e_attn + DD, r_attn, r_attn + DD };
    #pragma unroll
    for (int k = 0; k < 4; k++) {
        float4 a = ((const float4*)av[k])[lane];
        float d = nv.x * a.x + nv.y * a.y + nv.z * a.z + nv.w * a.w;
        d = wsum(d);
        if (lane == 0) g_rel_w[k][w] = __expf(d);
    }
}

// Normalize proxies, store transposed: pnormT[enc][i*64 + p]
__global__ void prep_proxy_kernel(const float* __restrict__ e_proxy,
                                  const float* __restrict__ r_proxy) {
    int w = (blockIdx.x * blockDim.x + threadIdx.x) >> 5;
    int lane = threadIdx.x & 31;
    if (w >= 2 * NP) return;
    int enc = w >> 6, p = w & 63;
    const float* src = (enc == 0 ? e_proxy : r_proxy) + (size_t)p * F3;
    float vals[12];
    float ss = 0.f;
    #pragma unroll
    for (int k = 0; k < 12; k++) { vals[k] = src[lane + 32 * k]; ss += vals[k] * vals[k]; }
    ss = wsum(ss);
    float inv = 1.f / fmaxf(sqrtf(ss), EPS);
    #pragma unroll
    for (int k = 0; k < 12; k++) g_pnormT[enc][(lane + 32 * k) * NP + p] = vals[k] * inv;
}

// ----------------------------------------------------------------------------
// CSR construction
// ----------------------------------------------------------------------------
__global__ void zero_cnt_kernel() {
    int i = blockIdx.x * blockDim.x + threadIdx.x;
    int stride = gridDim.x * blockDim.x;
    for (; i < 3 * NN; i += stride) ((int*)g_cnt)[i] = 0;
}

__global__ void count_kernel(const int* __restrict__ ent_adj,
                             const int* __restrict__ rel_adj,
                             const int* __restrict__ adj_list) {
    int t = blockIdx.x * blockDim.x + threadIdx.x;
    if (t >= TT) return;
    atomicAdd(&g_cnt[0][ent_adj[t]], 1);
    atomicAdd(&g_cnt[1][rel_adj[t]], 1);
    atomicAdd(&g_cnt[2][adj_list[t]], 1);
}

// Level 1: per-block inclusive scan; write local exclusive + block totals
__global__ void scan_local_kernel() {
    __shared__ int sm[1024];
    int a = blockIdx.y;
    int i = blockIdx.x * 1024 + threadIdx.x;
    int tid = threadIdx.x;
    int v = (i < NN) ? g_cnt[a][i] : 0;
    sm[tid] = v;
    __syncthreads();
    #pragma unroll
    for (int off = 1; off < 1024; off <<= 1) {
        int t = (tid >= off) ? sm[tid - off] : 0;
        __syncthreads();
        sm[tid] += t;
        __syncthreads();
    }
    if (i < NN) g_rowptr[a][i] = sm[tid] - v;   // local exclusive
    if (tid == 1023) g_bsum[a][blockIdx.x] = sm[1023];
}

// Level 2: scan block sums (tiny: 3 x 40)
__global__ void scan_bsum_kernel() {
    int a = threadIdx.x;
    if (a >= 3) return;
    int run = 0;
    for (int b = 0; b < NBLK; b++) { g_boff[a][b] = run; run += g_bsum[a][b]; }
    g_rowptr[a][NN] = run;
}

// Level 3: add block offsets, init cursors
__global__ void scan_add_kernel() {
    int a = blockIdx.y;
    int i = blockIdx.x * 1024 + threadIdx.x;
    if (i >= NN) return;
    int v = g_rowptr[a][i] + g_boff[a][blockIdx.x];
    g_rowptr[a][i] = v;
    g_cur[a][i] = v;
}

__global__ void fill_kernel(const int* __restrict__ ent_adj,
                            const int* __restrict__ rel_adj,
                            const int* __restrict__ adj_list,
                            const int* __restrict__ r_index,
                            const float* __restrict__ r_val) {
    int t = blockIdx.x * blockDim.x + threadIdx.x;
    if (t >= TT) return;
    {
        int row = ent_adj[t];
        int pos = atomicAdd(&g_cur[0][row], 1);
        g_eA_col[pos] = ent_adj[TT + t];
    }
    {
        int row = rel_adj[t];
        int pos = atomicAdd(&g_cur[1][row], 1);
        g_eB_col[pos] = rel_adj[TT + t];
    }
    {
        int row = adj_list[t];
        int pos = atomicAdd(&g_cur[2][row], 1);
        g_eC_col[pos] = adj_list[TT + t];
        int rel = r_index[TT + t];
        g_eC_rel[pos] = (r_val[t] > 0.f) ? rel : -1;
    }
}

// ----------------------------------------------------------------------------
// _avg + tanh: feats0 = tanh(mean over neighbors of emb[col]); warp per row
// ----------------------------------------------------------------------------
__global__ void avg_kernel(int which,                  // 0: ent CSR, 1: rel CSR
                           const float* __restrict__ emb,
                           float* __restrict__ dst,    // g_fA
                           float* __restrict__ outp) { // d_out + enc*384 (level 0)
    int w = (blockIdx.x * blockDim.x + threadIdx.x) >> 5;
    int lane = threadIdx.x & 31;
    if (w >= NN) return;
    int beg = g_rowptr[which][w], end = g_rowptr[which][w + 1];
    const int* col = (which == 0) ? g_eA_col : g_eB_col;
    float4 acc = make_float4(0.f, 0.f, 0.f, 0.f);
    for (int e = beg; e < end; e++) {
        int c = col[e];
        float4 nb = ((const float4*)emb)[c * 32 + lane];
        acc.x += nb.x; acc.y += nb.y; acc.z += nb.z; acc.w += nb.w;
    }
    int deg = end - beg;
    float inv = deg > 0 ? 1.f / (float)deg : 0.f;
    float4 o = make_float4(tanhf(acc.x * inv), tanhf(acc.y * inv),
                           tanhf(acc.z * inv), tanhf(acc.w * inv));
    ((float4*)dst)[w * 32 + lane] = o;
    *(float4*)(outp + (size_t)w * 768 + lane * 4) = o;
}

// ----------------------------------------------------------------------------
// One NR attention layer, single pass:
//  feats = tanh( sum_e w_e * (nb - 2(nb.rv)rv) / sum_e w_e ), w_e = exp(logit[rel_e])
// ----------------------------------------------------------------------------
__global__ void nr_layer_kernel(const float* __restrict__ src,
                                float* __restrict__ dst,
                                float* __restrict__ outp,  // d_out slice for this level
                                const float* __restrict__ wexp) {
    int w = (blockIdx.x * blockDim.x + threadIdx.x) >> 5;
    int lane = threadIdx.x & 31;
    if (w >= NN) return;
    int beg = g_rowptr[2][w], end = g_rowptr[2][w + 1];
    float4 acc = make_float4(0.f, 0.f, 0.f, 0.f);
    float s = 0.f;
    for (int e = beg; e < end; e++) {
        int c = g_eC_col[e];
        int rel = g_eC_rel[e];
        float4 nb = ((const float4*)src)[c * 32 + lane];
        float4 rv = rel >= 0 ? ((const float4*)g_rel_norm)[rel * 32 + lane]
                             : make_float4(0.f, 0.f, 0.f, 0.f);
        float wgt = rel >= 0 ? wexp[rel] : 1.f;
        float d = nb.x * rv.x + nb.y * rv.y + nb.z * rv.z + nb.w * rv.w;
        d = wsum(d);
        float c2 = 2.f * d;
        acc.x += wgt * (nb.x - c2 * rv.x);
        acc.y += wgt * (nb.y - c2 * rv.y);
        acc.z += wgt * (nb.z - c2 * rv.z);
        acc.w += wgt * (nb.w - c2 * rv.w);
        s += wgt;
    }
    float inv = (beg < end) ? 1.f / s : 0.f;
    float4 o = make_float4(tanhf(acc.x * inv), tanhf(acc.y * inv),
                           tanhf(acc.z * inv), tanhf(acc.w * inv));
    ((float4*)dst)[w * 32 + lane] = o;
    *(float4*)(outp + (size_t)w * 768 + lane * 4) = o;
}

// ----------------------------------------------------------------------------
// Proxy matching: pf = out - softmax(l2norm(out) @ pnorm^T) @ proxy. Warp/row.
// blockIdx.y = encoder (0: ent / 1: rel)
// ----------------------------------------------------------------------------
__global__ void epi1_kernel(float* __restrict__ outfull,       // d_out
                            const float* __restrict__ e_proxy,
                            const float* __restrict__ r_proxy) {
    __shared__ float s_out[8][F3];
    __shared__ float s_pa[8][NP];
    int enc = blockIdx.y;
    int wl = threadIdx.x >> 5;
    int lane = threadIdx.x & 31;
    int r = blockIdx.x * 8 + wl;
    if (r >= NN) return;
    const float* proxy = enc == 0 ? e_proxy : r_proxy;
    const float* orow = outfull + (size_t)r * 768 + enc * F3;
    const float* pT = g_pnormT[enc];
    float ov[12];
    float ss = 0.f;
    #pragma unroll
    for (int k = 0; k < 12; k++) {
        float v = orow[lane + 32 * k];
        ov[k] = v;
        s_out[wl][lane + 32 * k] = v;
        ss += v * v;
    }
    ss = wsum(ss);
    float invn = 1.f / fmaxf(sqrtf(ss), EPS);
    __syncwarp();
    float d0 = 0.f, d1 = 0.f;
    #pragma unroll 4
    for (int i = 0; i < F3; i++) {
        float o = s_out[wl][i];
        d0 += o * pT[i * NP + lane];
        d1 += o * pT[i * NP + lane + 32];
    }
    d0 *= invn; d1 *= invn;
    float mx = wmax(fmaxf(d0, d1));
    float e0 = __expf(d0 - mx), e1 = __expf(d1 - mx);
    float s = wsum(e0 + e1);
    float sinv = 1.f / s;
    s_pa[wl][lane] = e0 * sinv;
    s_pa[wl][lane + 32] = e1 * sinv;
    __syncwarp();
    float* pfout = g_pf[enc] + (size_t)r * F3;
    #pragma unroll
    for (int k = 0; k < 12; k++) {
        int i = lane + 32 * k;
        float a = 0.f;
        #pragma unroll 8
        for (int j = 0; j < NP; j++) a += s_pa[wl][j] * proxy[(size_t)j * F3 + i];
        pfout[i] = ov[k] - a;
    }
}

// ----------------------------------------------------------------------------
// Gating GEMM (fused, SIMT fp32): logits = pf @ gate + bias; g = sigmoid;
// final = g*out + (1-g)*pf, in-place to outbase slice.
// 128x128 tile, 8x8/thread, BK=16, ping-pong smem, 256 threads.
// blockIdx.z = encoder.
// ----------------------------------------------------------------------------
#define BM 128
#define BN 128
#define BK 16
__global__ void __launch_bounds__(256, 2)
gemm_gate_kernel(float* __restrict__ outfull,         // d_out (or probe sink)
                 const float* __restrict__ e_gate,
                 const float* __restrict__ r_gate,
                 const float* __restrict__ e_bias,
                 const float* __restrict__ r_bias) {
    __shared__ float As[2][BK][BM];
    __shared__ float Bs[2][BK][BN];
    int enc = blockIdx.z;
    const float* gate = enc == 0 ? e_gate : r_gate;
    const float* bias = enc == 0 ? e_bias : r_bias;
    const float* pf = g_pf[enc];
    float* outbase = outfull + enc * F3;

    int bx = blockIdx.x;  // 0..2
    int by = blockIdx.y;  // 0..312
    int tid = threadIdx.x;
    int tx = tid & 15;          // n-group: 8 consecutive cols
    int ty = tid >> 4;          // m-group: 8 consecutive rows
    int m0 = by * BM, n0 = bx * BN;
    float c[8][8];
    #pragma unroll
    for (int i = 0; i < 8; i++)
        #pragma unroll
        for (int j = 0; j < 8; j++) c[i][j] = 0.f;

    // A slab load: 128 rows x 16 k = 512 float4; 2 per thread
    int am = tid >> 1;              // 0..127
    int ak = (tid & 1) * 8;         // 0 or 8 (two float4 at ak, ak+4)
    // B slab load: 16 k x 128 n = 512 float4; 2 per thread
    int bk = tid >> 4;              // 0..15
    int bn = (tid & 15) * 8;        // 0..120 (two float4)

    // Preload slab 0
    {
        const float* arow = &pf[(size_t)(m0 + am) * F3 + ak];
        float4 a0 = *(const float4*)(arow);
        float4 a1 = *(const float4*)(arow + 4);
        As[0][ak + 0][am] = a0.x; As[0][ak + 1][am] = a0.y;
        As[0][ak + 2][am] = a0.z; As[0][ak + 3][am] = a0.w;
        As[0][ak + 4][am] = a1.x; As[0][ak + 5][am] = a1.y;
        As[0][ak + 6][am] = a1.z; As[0][ak + 7][am] = a1.w;
        const float* brow = &gate[(size_t)bk * F3 + n0 + bn];
        *(float4*)&Bs[0][bk][bn] = *(const float4*)(brow);
        *(float4*)&Bs[0][bk][bn + 4] = *(const float4*)(brow + 4);
    }
    __syncthreads();

    const int NITER = F3 / BK;  // 24
    #pragma unroll 1
    for (int it = 0; it < NITER; it++) {
        int buf = it & 1;
        // Prefetch next slab into registers
        float4 na0, na1, nb0, nb1;
        if (it + 1 < NITER) {
            int k0 = (it + 1) * BK;
            const float* arow = &pf[(size_t)(m0 + am) * F3 + k0 + ak];
            na0 = *(const float4*)(arow);
            na1 = *(const float4*)(arow + 4);
            const float* brow = &gate[(size_t)(k0 + bk) * F3 + n0 + bn];
            nb0 = *(const float4*)(brow);
            nb1 = *(const float4*)(brow + 4);
        }
        // Compute on current buffer
        #pragma unroll
        for (int k = 0; k < BK; k++) {
            float a[8], b[8];
            *(float4*)&a[0] = *(const float4*)&As[buf][k][ty * 8];
            *(float4*)&a[4] = *(const float4*)&As[buf][k][ty * 8 + 4];
            *(float4*)&b[0] = *(const float4*)&Bs[buf][k][tx * 8];
            *(float4*)&b[4] = *(const float4*)&Bs[buf][k][tx * 8 + 4];
            #pragma unroll
            for (int i = 0; i < 8; i++)
                #pragma unroll
                for (int j = 0; j < 8; j++) c[i][j] += a[i] * b[j];
        }
        // Store prefetched slab into other buffer (no conflict with readers)
        if (it + 1 < NITER) {
            int nb_ = buf ^ 1;
            As[nb_][ak + 0][am] = na0.x; As[nb_][ak + 1][am] = na0.y;
            As[nb_][ak + 2][am] = na0.z; As[nb_][ak + 3][am] = na0.w;
            As[nb_][ak + 4][am] = na1.x; As[nb_][ak + 5][am] = na1.y;
            As[nb_][ak + 6][am] = na1.z; As[nb_][ak + 7][am] = na1.w;
            *(float4*)&Bs[nb_][bk][bn] = nb0;
            *(float4*)&Bs[nb_][bk][bn + 4] = nb1;
            __syncthreads();
        }
    }

    // Epilogue: sigmoid gate + blend, float4 stores
    float bv[8];
    *(float4*)&bv[0] = *(const float4*)&bias[n0 + tx * 8];
    *(float4*)&bv[4] = *(const float4*)&bias[n0 + tx * 8 + 4];
    #pragma unroll
    for (int i = 0; i < 8; i++) {
        int m = m0 + ty * 8 + i;
        if (m >= NN) break;
        float* orow = outbase + (size_t)m * 768 + n0 + tx * 8;
        const float* pfrow = &pf[(size_t)m * F3 + n0 + tx * 8];
        #pragma unroll
        for (int h = 0; h < 2; h++) {
            float4 o4 = *(const float4*)(orow + h * 4);
            float4 p4 = *(const float4*)(pfrow + h * 4);
            float r[4];
            #pragma unroll
            for (int q = 0; q < 4; q++) {
                int j = h * 4 + q;
                float logit = c[i][j] + bv[j];
                float g = 1.f / (1.f + __expf(-logit));
                float o = (&o4.x)[q];
                float pfv = (&p4.x)[q];
                r[q] = g * o + (1.f - g) * pfv;
            }
            *(float4*)(orow + h * 4) = make_float4(r[0], r[1], r[2], r[3]);
        }
    }
}

// ----------------------------------------------------------------------------
// Host
// ----------------------------------------------------------------------------
extern "C" void kernel_launch(void* const* d_in, const int* in_sizes, int n_in,
                              void* d_out, int out_size) {
    // Bind inputs by size (robust to whether scalar ints appear in the list)
    const int* ent_adj = nullptr;
    const int* rel_adj = nullptr;
    const int* adj_list = nullptr;
    const int* r_index = nullptr;
    const float* r_val = nullptr;
    const float* ent_emb = nullptr;
    const float* rel_emb = nullptr;
    const float* e_attn = nullptr; const float* r_attn = nullptr;
    const float* e_gate = nullptr; const float* r_gate = nullptr;
    const float* e_proxy = nullptr; const float* r_proxy = nullptr;
    const float* e_bias = nullptr; const float* r_bias = nullptr;
    int c12 = 0, c256 = 0, cgate = 0, cprox = 0, cbias = 0;
    for (int i = 0; i < n_in; i++) {
        int sz = in_sizes[i];
        void* p = d_in[i];
        switch (sz) {
            case 2 * TT:
                if (c12 == 0) ent_adj = (const int*)p;
                else if (c12 == 1) rel_adj = (const int*)p;
                else if (c12 == 2) adj_list = (const int*)p;
                else r_index = (const int*)p;
                c12++;
                break;
            case TT: r_val = (const float*)p; break;
            case NN * DD: ent_emb = (const float*)p; break;
            case RR * DD: rel_emb = (const float*)p; break;
            case 2 * DD:
                if (c256 == 0) e_attn = (const float*)p; else r_attn = (const float*)p;
                c256++;
                break;
            case F3 * F3:
                if (cgate == 0) e_gate = (const float*)p; else r_gate = (const float*)p;
                cgate++;
                break;
            case NP * F3:
                if (cprox == 0) e_proxy = (const float*)p; else r_proxy = (const float*)p;
                cprox++;
                break;
            case F3:
                if (cbias == 0) e_bias = (const float*)p; else r_bias = (const float*)p;
                cbias++;
                break;
            default: break; // scalars / mask: unused
        }
    }
    float* out = (float*)d_out;

    float* d_fA; cudaGetSymbolAddress((void**)&d_fA, g_fA);
    float* d_fB; cudaGetSymbolAddress((void**)&d_fB, g_fB);
    float* d_w;  cudaGetSymbolAddress((void**)&d_w, g_rel_w);
    float* d_dummy; cudaGetSymbolAddress((void**)&d_dummy, g_dummy);

    // Prep  (my launch indices 0,1)
    prep_rel_kernel<<<(RR + 7) / 8, 256>>>(rel_emb, e_attn, r_attn);
    prep_proxy_kernel<<<16, 256>>>(e_proxy, r_proxy);

    // index 2
    zero_cnt_kernel<<<256, 256>>>();

    // index 3 == global ncu slot 5: GEMM PROBE (half the real GEMM work, z=1).
    // Reads g_pf[0] (content irrelevant, timing data-independent), blends into
    // g_dummy which nothing else reads. Gives ncu metrics + wall-clock delta.
    gemm_gate_kernel<<<dim3(F3 / BN, (NN + BM - 1) / BM, 1), 256>>>(
        d_dummy, e_gate, r_gate, e_bias, r_bias);

    // CSR build (3 adjacencies)
    count_kernel<<<(TT + 255) / 256, 256>>>(ent_adj, rel_adj, adj_list);
    scan_local_kernel<<<dim3(NBLK, 3), 1024>>>();
    scan_bsum_kernel<<<1, 32>>>();
    scan_add_kernel<<<dim3(NBLK, 3), 1024>>>();
    fill_kernel<<<(TT + 255) / 256, 256>>>(ent_adj, rel_adj, adj_list, r_index, r_val);

    const int ROWBLK = (NN + 7) / 8;  // warp-per-row, 8 warps/block

    // ---------------- Edge phase: Encoder E then R ----------------
    avg_kernel<<<ROWBLK, 256>>>(0, ent_emb, d_fA, out + 0);
    nr_layer_kernel<<<ROWBLK, 256>>>(d_fA, d_fB, out + 128, d_w + 0 * RR);
    nr_layer_kernel<<<ROWBLK, 256>>>(d_fB, d_fA, out + 256, d_w + 1 * RR);

    avg_kernel<<<ROWBLK, 256>>>(1, rel_emb, d_fA, out + 384);
    nr_layer_kernel<<<ROWBLK, 256>>>(d_fA, d_fB, out + 384 + 128, d_w + 2 * RR);
    nr_layer_kernel<<<ROWBLK, 256>>>(d_fB, d_fA, out + 384 + 256, d_w + 3 * RR);

    // ---------------- Epilogue: both encoders in single launches ----------------
    epi1_kernel<<<dim3(ROWBLK, 2), 256>>>(out, e_proxy, r_proxy);
    gemm_gate_kernel<<<dim3(F3 / BN, (NN + BM - 1) / BM, 2), 256>>>(
        out, e_gate, r_gate, e_bias, r_bias);
}

// round 13
// speedup vs baseline: 1.1729x; 1.1729x over previous
#include <cuda_runtime.h>
#include <math.h>
#include <stdint.h>

// Problem constants (fixed by the dataset)
#define NN 40000      // node_size
#define RR 2000       // rel_size
#define TT 600000     // triple_size
#define DD 128        // DIM
#define F3 384        // DIM*(DEPTH+1)
#define NP 64         // num proxies
#define EPS 1e-12f
#define NBLK 40       // ceil(NN/1024)
#define NPAD 40064    // NN padded to 128-row multiple for GEMM tiles

// ----------------------------------------------------------------------------
// Device scratch (static: no allocation allowed; zero-initialized at load)
// ----------------------------------------------------------------------------
__device__ float g_rel_norm[RR * DD];        // normalized rel_emb
__device__ float g_rel_w[4][RR];             // exp(edge-attn logit) per [enc*2+layer][rel]
__device__ float g_pnormT[2][F3 * NP];       // transposed normalized proxies [i*64+p]

__device__ int g_cnt[3][NN];                 // per-row degree (3 adjacencies)
__device__ int g_rowptr[3][NN + 1];
__device__ int g_cur[3][NN];
__device__ int g_bsum[3][NBLK];
__device__ int g_boff[3][NBLK];

__device__ int g_eA_col[TT];                 // ent_adj cols (CSR order)
__device__ int g_eB_col[TT];                 // rel_adj cols (rel ids)
__device__ int g_eC_col[TT];                 // adj_list cols (node ids)
__device__ int g_eC_rel[TT];                 // rel id, or -1 if r_val == 0

__device__ float g_fA[NN * DD];              // ping
__device__ float g_fB[NN * DD];              // pong
__device__ float g_pf[2][(size_t)NPAD * F3]; // proxy-filtered per encoder (pad rows stay 0)

// ----------------------------------------------------------------------------
// Warp helpers
// ----------------------------------------------------------------------------
__device__ __forceinline__ float wsum(float v) {
    #pragma unroll
    for (int o = 16; o; o >>= 1) v += __shfl_xor_sync(0xffffffffu, v, o);
    return v;
}
__device__ __forceinline__ float wmax(float v) {
    #pragma unroll
    for (int o = 16; o; o >>= 1) v = fmaxf(v, __shfl_xor_sync(0xffffffffu, v, o));
    return v;
}

// ----------------------------------------------------------------------------
// Prep: normalized relation embeddings + per-relation attention exp-weights
// ----------------------------------------------------------------------------
__global__ void prep_rel_kernel(const float* __restrict__ rel_emb,
                                const float* __restrict__ e_attn,
                                const float* __restrict__ r_attn) {
    int w = (blockIdx.x * blockDim.x + threadIdx.x) >> 5;
    int lane = threadIdx.x & 31;
    if (w >= RR) return;
    float4 v = ((const float4*)rel_emb)[w * 32 + lane];
    float ss = v.x * v.x + v.y * v.y + v.z * v.z + v.w * v.w;
    ss = wsum(ss);
    float inv = 1.f / fmaxf(sqrtf(ss), EPS);
    float4 nv = make_float4(v.x * inv, v.y * inv, v.z * inv, v.w * inv);
    ((float4*)g_rel_norm)[w * 32 + lane] = nv;
    const float* av[4] = { e_attn, e_attn + DD, r_attn, r_attn + DD };
    #pragma unroll
    for (int k = 0; k < 4; k++) {
        float4 a = ((const float4*)av[k])[lane];
        float d = nv.x * a.x + nv.y * a.y + nv.z * a.z + nv.w * a.w;
        d = wsum(d);
        if (lane == 0) g_rel_w[k][w] = __expf(d);
    }
}

// Normalize proxies, store transposed: pnormT[enc][i*64 + p]
__global__ void prep_proxy_kernel(const float* __restrict__ e_proxy,
                                  const float* __restrict__ r_proxy) {
    int w = (blockIdx.x * blockDim.x + threadIdx.x) >> 5;
    int lane = threadIdx.x & 31;
    if (w >= 2 * NP) return;
    int enc = w >> 6, p = w & 63;
    const float* src = (enc == 0 ? e_proxy : r_proxy) + (size_t)p * F3;
    float vals[12];
    float ss = 0.f;
    #pragma unroll
    for (int k = 0; k < 12; k++) { vals[k] = src[lane + 32 * k]; ss += vals[k] * vals[k]; }
    ss = wsum(ss);
    float inv = 1.f / fmaxf(sqrtf(ss), EPS);
    #pragma unroll
    for (int k = 0; k < 12; k++) g_pnormT[enc][(lane + 32 * k) * NP + p] = vals[k] * inv;
}

// ----------------------------------------------------------------------------
// CSR construction
// ----------------------------------------------------------------------------
__global__ void zero_cnt_kernel() {
    int i = blockIdx.x * blockDim.x + threadIdx.x;
    int stride = gridDim.x * blockDim.x;
    for (; i < 3 * NN; i += stride) ((int*)g_cnt)[i] = 0;
}

__global__ void count_kernel(const int* __restrict__ ent_adj,
                             const int* __restrict__ rel_adj,
                             const int* __restrict__ adj_list) {
    int t = blockIdx.x * blockDim.x + threadIdx.x;
    if (t >= TT) return;
    atomicAdd(&g_cnt[0][ent_adj[t]], 1);
    atomicAdd(&g_cnt[1][rel_adj[t]], 1);
    atomicAdd(&g_cnt[2][adj_list[t]], 1);
}

// Level 1: per-block inclusive scan; write local exclusive + block totals
__global__ void scan_local_kernel() {
    __shared__ int sm[1024];
    int a = blockIdx.y;
    int i = blockIdx.x * 1024 + threadIdx.x;
    int tid = threadIdx.x;
    int v = (i < NN) ? g_cnt[a][i] : 0;
    sm[tid] = v;
    __syncthreads();
    #pragma unroll
    for (int off = 1; off < 1024; off <<= 1) {
        int t = (tid >= off) ? sm[tid - off] : 0;
        __syncthreads();
        sm[tid] += t;
        __syncthreads();
    }
    if (i < NN) g_rowptr[a][i] = sm[tid] - v;   // local exclusive
    if (tid == 1023) g_bsum[a][blockIdx.x] = sm[1023];
}

// Level 2: scan block sums (tiny: 3 x 40)
__global__ void scan_bsum_kernel() {
    int a = threadIdx.x;
    if (a >= 3) return;
    int run = 0;
    for (int b = 0; b < NBLK; b++) { g_boff[a][b] = run; run += g_bsum[a][b]; }
    g_rowptr[a][NN] = run;
}

// Level 3: add block offsets, init cursors
__global__ void scan_add_kernel() {
    int a = blockIdx.y;
    int i = blockIdx.x * 1024 + threadIdx.x;
    if (i >= NN) return;
    int v = g_rowptr[a][i] + g_boff[a][blockIdx.x];
    g_rowptr[a][i] = v;
    g_cur[a][i] = v;
}

__global__ void fill_kernel(const int* __restrict__ ent_adj,
                            const int* __restrict__ rel_adj,
                            const int* __restrict__ adj_list,
                            const int* __restrict__ r_index,
                            const float* __restrict__ r_val) {
    int t = blockIdx.x * blockDim.x + threadIdx.x;
    if (t >= TT) return;
    {
        int row = ent_adj[t];
        int pos = atomicAdd(&g_cur[0][row], 1);
        g_eA_col[pos] = ent_adj[TT + t];
    }
    {
        int row = rel_adj[t];
        int pos = atomicAdd(&g_cur[1][row], 1);
        g_eB_col[pos] = rel_adj[TT + t];
    }
    {
        int row = adj_list[t];
        int pos = atomicAdd(&g_cur[2][row], 1);
        g_eC_col[pos] = adj_list[TT + t];
        int rel = r_index[TT + t];
        g_eC_rel[pos] = (r_val[t] > 0.f) ? rel : -1;
    }
}

// ----------------------------------------------------------------------------
// _avg + tanh: feats0 = tanh(mean over neighbors of emb[col]); warp per row.
// 4x unrolled: 4 independent gathers in flight.
// ----------------------------------------------------------------------------
__global__ void avg_kernel(int which,                  // 0: ent CSR, 1: rel CSR
                           const float* __restrict__ emb,
                           float* __restrict__ dst,    // g_fA
                           float* __restrict__ outp) { // d_out + enc*384 (level 0)
    int w = (blockIdx.x * blockDim.x + threadIdx.x) >> 5;
    int lane = threadIdx.x & 31;
    if (w >= NN) return;
    int beg = g_rowptr[which][w], end = g_rowptr[which][w + 1];
    const int* col = (which == 0) ? g_eA_col : g_eB_col;
    float4 acc = make_float4(0.f, 0.f, 0.f, 0.f);
    int e = beg;
    for (; e + 3 < end; e += 4) {
        int c0 = col[e], c1 = col[e + 1], c2 = col[e + 2], c3 = col[e + 3];
        float4 n0 = ((const float4*)emb)[c0 * 32 + lane];
        float4 n1 = ((const float4*)emb)[c1 * 32 + lane];
        float4 n2 = ((const float4*)emb)[c2 * 32 + lane];
        float4 n3 = ((const float4*)emb)[c3 * 32 + lane];
        acc.x += (n0.x + n1.x) + (n2.x + n3.x);
        acc.y += (n0.y + n1.y) + (n2.y + n3.y);
        acc.z += (n0.z + n1.z) + (n2.z + n3.z);
        acc.w += (n0.w + n1.w) + (n2.w + n3.w);
    }
    for (; e < end; e++) {
        float4 nb = ((const float4*)emb)[col[e] * 32 + lane];
        acc.x += nb.x; acc.y += nb.y; acc.z += nb.z; acc.w += nb.w;
    }
    int deg = end - beg;
    float inv = deg > 0 ? 1.f / (float)deg : 0.f;
    float4 o = make_float4(tanhf(acc.x * inv), tanhf(acc.y * inv),
                           tanhf(acc.z * inv), tanhf(acc.w * inv));
    ((float4*)dst)[w * 32 + lane] = o;
    *(float4*)(outp + (size_t)w * 768 + lane * 4) = o;
}

// ----------------------------------------------------------------------------
// One NR attention layer, single pass, 4x unrolled:
//  feats = tanh( sum_e w_e * (nb - 2(nb.rv)rv) / sum_e w_e ), w_e = exp(logit[rel_e])
// 4 independent gather+dot+butterfly chains in flight per iteration.
// ----------------------------------------------------------------------------
__global__ void nr_layer_kernel(const float* __restrict__ src,
                                float* __restrict__ dst,
                                float* __restrict__ outp,  // row-stride-768 sink
                                const float* __restrict__ wexp) {
    int w = (blockIdx.x * blockDim.x + threadIdx.x) >> 5;
    int lane = threadIdx.x & 31;
    if (w >= NN) return;
    int beg = g_rowptr[2][w], end = g_rowptr[2][w + 1];
    float4 acc = make_float4(0.f, 0.f, 0.f, 0.f);
    float s = 0.f;
    int e = beg;
    for (; e + 3 < end; e += 4) {
        int c0 = g_eC_col[e],     r0 = g_eC_rel[e];
        int c1 = g_eC_col[e + 1], r1 = g_eC_rel[e + 1];
        int c2 = g_eC_col[e + 2], r2 = g_eC_rel[e + 2];
        int c3 = g_eC_col[e + 3], r3 = g_eC_rel[e + 3];
        float4 n0 = ((const float4*)src)[c0 * 32 + lane];
        float4 n1 = ((const float4*)src)[c1 * 32 + lane];
        float4 n2 = ((const float4*)src)[c2 * 32 + lane];
        float4 n3 = ((const float4*)src)[c3 * 32 + lane];
        float4 v0 = r0 >= 0 ? ((const float4*)g_rel_norm)[r0 * 32 + lane]
                            : make_float4(0.f, 0.f, 0.f, 0.f);
        float4 v1 = r1 >= 0 ? ((const float4*)g_rel_norm)[r1 * 32 + lane]
                            : make_float4(0.f, 0.f, 0.f, 0.f);
        float4 v2 = r2 >= 0 ? ((const float4*)g_rel_norm)[r2 * 32 + lane]
                            : make_float4(0.f, 0.f, 0.f, 0.f);
        float4 v3 = r3 >= 0 ? ((const float4*)g_rel_norm)[r3 * 32 + lane]
                            : make_float4(0.f, 0.f, 0.f, 0.f);
        float w0 = r0 >= 0 ? wexp[r0] : 1.f;
        float w1 = r1 >= 0 ? wexp[r1] : 1.f;
        float w2 = r2 >= 0 ? wexp[r2] : 1.f;
        float w3 = r3 >= 0 ? wexp[r3] : 1.f;
        float d0 = n0.x * v0.x + n0.y * v0.y + n0.z * v0.z + n0.w * v0.w;
        float d1 = n1.x * v1.x + n1.y * v1.y + n1.z * v1.z + n1.w * v1.w;
        float d2 = n2.x * v2.x + n2.y * v2.y + n2.z * v2.z + n2.w * v2.w;
        float d3 = n3.x * v3.x + n3.y * v3.y + n3.z * v3.z + n3.w * v3.w;
        // four interleaved butterfly reductions (independent chains)
        #pragma unroll
        for (int o = 16; o; o >>= 1) {
            d0 += __shfl_xor_sync(0xffffffffu, d0, o);
            d1 += __shfl_xor_sync(0xffffffffu, d1, o);
            d2 += __shfl_xor_sync(0xffffffffu, d2, o);
            d3 += __shfl_xor_sync(0xffffffffu, d3, o);
        }
        float c20 = 2.f * d0, c21 = 2.f * d1, c22 = 2.f * d2, c23 = 2.f * d3;
        acc.x += w0 * (n0.x - c20 * v0.x);
        acc.y += w0 * (n0.y - c20 * v0.y);
        acc.z += w0 * (n0.z - c20 * v0.z);
        acc.w += w0 * (n0.w - c20 * v0.w);
        acc.x += w1 * (n1.x - c21 * v1.x);
        acc.y += w1 * (n1.y - c21 * v1.y);
        acc.z += w1 * (n1.z - c21 * v1.z);
        acc.w += w1 * (n1.w - c21 * v1.w);
        acc.x += w2 * (n2.x - c22 * v2.x);
        acc.y += w2 * (n2.y - c22 * v2.y);
        acc.z += w2 * (n2.z - c22 * v2.z);
        acc.w += w2 * (n2.w - c22 * v2.w);
        acc.x += w3 * (n3.x - c23 * v3.x);
        acc.y += w3 * (n3.y - c23 * v3.y);
        acc.z += w3 * (n3.z - c23 * v3.z);
        acc.w += w3 * (n3.w - c23 * v3.w);
        s += (w0 + w1) + (w2 + w3);
    }
    for (; e < end; e++) {
        int c = g_eC_col[e];
        int rel = g_eC_rel[e];
        float4 nb = ((const float4*)src)[c * 32 + lane];
        float4 rv = rel >= 0 ? ((const float4*)g_rel_norm)[rel * 32 + lane]
                             : make_float4(0.f, 0.f, 0.f, 0.f);
        float wgt = rel >= 0 ? wexp[rel] : 1.f;
        float d = nb.x * rv.x + nb.y * rv.y + nb.z * rv.z + nb.w * rv.w;
        d = wsum(d);
        float c2 = 2.f * d;
        acc.x += wgt * (nb.x - c2 * rv.x);
        acc.y += wgt * (nb.y - c2 * rv.y);
        acc.z += wgt * (nb.z - c2 * rv.z);
        acc.w += wgt * (nb.w - c2 * rv.w);
        s += wgt;
    }
    float inv = (beg < end) ? 1.f / s : 0.f;
    float4 o = make_float4(tanhf(acc.x * inv), tanhf(acc.y * inv),
                           tanhf(acc.z * inv), tanhf(acc.w * inv));
    ((float4*)dst)[w * 32 + lane] = o;
    *(float4*)(outp + (size_t)w * 768 + lane * 4) = o;
}

// ----------------------------------------------------------------------------
// Proxy matching: pf = out - softmax(l2norm(out) @ pnorm^T) @ proxy. Warp/row.
// blockIdx.y = encoder (0: ent / 1: rel)
// ----------------------------------------------------------------------------
__global__ void epi1_kernel(float* __restrict__ outfull,       // d_out
                            const float* __restrict__ e_proxy,
                            const float* __restrict__ r_proxy) {
    __shared__ float s_out[8][F3];
    __shared__ float s_pa[8][NP];
    int enc = blockIdx.y;
    int wl = threadIdx.x >> 5;
    int lane = threadIdx.x & 31;
    int r = blockIdx.x * 8 + wl;
    if (r >= NN) return;
    const float* proxy = enc == 0 ? e_proxy : r_proxy;
    const float* orow = outfull + (size_t)r * 768 + enc * F3;
    const float* pT = g_pnormT[enc];
    float ov[12];
    float ss = 0.f;
    #pragma unroll
    for (int k = 0; k < 12; k++) {
        float v = orow[lane + 32 * k];
        ov[k] = v;
        s_out[wl][lane + 32 * k] = v;
        ss += v * v;
    }
    ss = wsum(ss);
    float invn = 1.f / fmaxf(sqrtf(ss), EPS);
    __syncwarp();
    float d0 = 0.f, d1 = 0.f;
    #pragma unroll 4
    for (int i = 0; i < F3; i++) {
        float o = s_out[wl][i];
        d0 += o * pT[i * NP + lane];
        d1 += o * pT[i * NP + lane + 32];
    }
    d0 *= invn; d1 *= invn;
    float mx = wmax(fmaxf(d0, d1));
    float e0 = __expf(d0 - mx), e1 = __expf(d1 - mx);
    float s = wsum(e0 + e1);
    float sinv = 1.f / s;
    s_pa[wl][lane] = e0 * sinv;
    s_pa[wl][lane + 32] = e1 * sinv;
    __syncwarp();
    float* pfout = g_pf[enc] + (size_t)r * F3;
    #pragma unroll
    for (int k = 0; k < 12; k++) {
        int i = lane + 32 * k;
        float a = 0.f;
        #pragma unroll 8
        for (int j = 0; j < NP; j++) a += s_pa[wl][j] * proxy[(size_t)j * F3 + i];
        pfout[i] = ov[k] - a;
    }
}

// ----------------------------------------------------------------------------
// Gating GEMM (fused, SIMT fp32): logits = pf @ gate + bias; g = sigmoid;
// final = g*out + (1-g)*pf, in-place to outbase slice.
// 128x128 tile, 8x8/thread, BK=16, ping-pong smem, 256 threads.
// blockIdx.z = encoder.
// ----------------------------------------------------------------------------
#define BM 128
#define BN 128
#define BK 16
__global__ void __launch_bounds__(256, 2)
gemm_gate_kernel(float* __restrict__ outfull,         // d_out
                 const float* __restrict__ e_gate,
                 const float* __restrict__ r_gate,
                 const float* __restrict__ e_bias,
                 const float* __restrict__ r_bias) {
    __shared__ float As[2][BK][BM];
    __shared__ float Bs[2][BK][BN];
    int enc = blockIdx.z;
    const float* gate = enc == 0 ? e_gate : r_gate;
    const float* bias = enc == 0 ? e_bias : r_bias;
    const float* pf = g_pf[enc];
    float* outbase = outfull + enc * F3;

    int bx = blockIdx.x;  // 0..2
    int by = blockIdx.y;  // 0..312
    int tid = threadIdx.x;
    int tx = tid & 15;          // n-group: 8 consecutive cols
    int ty = tid >> 4;          // m-group: 8 consecutive rows
    int m0 = by * BM, n0 = bx * BN;
    float c[8][8];
    #pragma unroll
    for (int i = 0; i < 8; i++)
        #pragma unroll
        for (int j = 0; j < 8; j++) c[i][j] = 0.f;

    // A slab load: 128 rows x 16 k = 512 float4; 2 per thread
    int am = tid >> 1;              // 0..127
    int ak = (tid & 1) * 8;         // 0 or 8 (two float4 at ak, ak+4)
    // B slab load: 16 k x 128 n = 512 float4; 2 per thread
    int bk = tid >> 4;              // 0..15
    int bn = (tid & 15) * 8;        // 0..120 (two float4)

    // Preload slab 0
    {
        const float* arow = &pf[(size_t)(m0 + am) * F3 + ak];
        float4 a0 = *(const float4*)(arow);
        float4 a1 = *(const float4*)(arow + 4);
        As[0][ak + 0][am] = a0.x; As[0][ak + 1][am] = a0.y;
        As[0][ak + 2][am] = a0.z; As[0][ak + 3][am] = a0.w;
        As[0][ak + 4][am] = a1.x; As[0][ak + 5][am] = a1.y;
        As[0][ak + 6][am] = a1.z; As[0][ak + 7][am] = a1.w;
        const float* brow = &gate[(size_t)bk * F3 + n0 + bn];
        *(float4*)&Bs[0][bk][bn] = *(const float4*)(brow);
        *(float4*)&Bs[0][bk][bn + 4] = *(const float4*)(brow + 4);
    }
    __syncthreads();

    const int NITER = F3 / BK;  // 24
    #pragma unroll 1
    for (int it = 0; it < NITER; it++) {
        int buf = it & 1;
        // Prefetch next slab into registers
        float4 na0, na1, nb0, nb1;
        if (it + 1 < NITER) {
            int k0 = (it + 1) * BK;
            const float* arow = &pf[(size_t)(m0 + am) * F3 + k0 + ak];
            na0 = *(const float4*)(arow);
            na1 = *(const float4*)(arow + 4);
            const float* brow = &gate[(size_t)(k0 + bk) * F3 + n0 + bn];
            nb0 = *(const float4*)(brow);
            nb1 = *(const float4*)(brow + 4);
        }
        // Compute on current buffer
        #pragma unroll
        for (int k = 0; k < BK; k++) {
            float a[8], b[8];
            *(float4*)&a[0] = *(const float4*)&As[buf][k][ty * 8];
            *(float4*)&a[4] = *(const float4*)&As[buf][k][ty * 8 + 4];
            *(float4*)&b[0] = *(const float4*)&Bs[buf][k][tx * 8];
            *(float4*)&b[4] = *(const float4*)&Bs[buf][k][tx * 8 + 4];
            #pragma unroll
            for (int i = 0; i < 8; i++)
                #pragma unroll
                for (int j = 0; j < 8; j++) c[i][j] += a[i] * b[j];
        }
        // Store prefetched slab into other buffer (no conflict with readers)
        if (it + 1 < NITER) {
            int nb_ = buf ^ 1;
            As[nb_][ak + 0][am] = na0.x; As[nb_][ak + 1][am] = na0.y;
            As[nb_][ak + 2][am] = na0.z; As[nb_][ak + 3][am] = na0.w;
            As[nb_][ak + 4][am] = na1.x; As[nb_][ak + 5][am] = na1.y;
            As[nb_][ak + 6][am] = na1.z; As[nb_][ak + 7][am] = na1.w;
            *(float4*)&Bs[nb_][bk][bn] = nb0;
            *(float4*)&Bs[nb_][bk][bn + 4] = nb1;
            __syncthreads();
        }
    }

    // Epilogue: sigmoid gate + blend, float4 stores
    float bv[8];
    *(float4*)&bv[0] = *(const float4*)&bias[n0 + tx * 8];
    *(float4*)&bv[4] = *(const float4*)&bias[n0 + tx * 8 + 4];
    #pragma unroll
    for (int i = 0; i < 8; i++) {
        int m = m0 + ty * 8 + i;
        if (m >= NN) break;
        float* orow = outbase + (size_t)m * 768 + n0 + tx * 8;
        const float* pfrow = &pf[(size_t)m * F3 + n0 + tx * 8];
        #pragma unroll
        for (int h = 0; h < 2; h++) {
            float4 o4 = *(const float4*)(orow + h * 4);
            float4 p4 = *(const float4*)(pfrow + h * 4);
            float r[4];
            #pragma unroll
            for (int q = 0; q < 4; q++) {
                int j = h * 4 + q;
                float logit = c[i][j] + bv[j];
                float g = 1.f / (1.f + __expf(-logit));
                float o = (&o4.x)[q];
                float pfv = (&p4.x)[q];
                r[q] = g * o + (1.f - g) * pfv;
            }
            *(float4*)(orow + h * 4) = make_float4(r[0], r[1], r[2], r[3]);
        }
    }
}

// ----------------------------------------------------------------------------
// Host
// ----------------------------------------------------------------------------
extern "C" void kernel_launch(void* const* d_in, const int* in_sizes, int n_in,
                              void* d_out, int out_size) {
    // Bind inputs by size (robust to whether scalar ints appear in the list)
    const int* ent_adj = nullptr;
    const int* rel_adj = nullptr;
    const int* adj_list = nullptr;
    const int* r_index = nullptr;
    const float* r_val = nullptr;
    const float* ent_emb = nullptr;
    const float* rel_emb = nullptr;
    const float* e_attn = nullptr; const float* r_attn = nullptr;
    const float* e_gate = nullptr; const float* r_gate = nullptr;
    const float* e_proxy = nullptr; const float* r_proxy = nullptr;
    const float* e_bias = nullptr; const float* r_bias = nullptr;
    int c12 = 0, c256 = 0, cgate = 0, cprox = 0, cbias = 0;
    for (int i = 0; i < n_in; i++) {
        int sz = in_sizes[i];
        void* p = d_in[i];
        switch (sz) {
            case 2 * TT:
                if (c12 == 0) ent_adj = (const int*)p;
                else if (c12 == 1) rel_adj = (const int*)p;
                else if (c12 == 2) adj_list = (const int*)p;
                else r_index = (const int*)p;
                c12++;
                break;
            case TT: r_val = (const float*)p; break;
            case NN * DD: ent_emb = (const float*)p; break;
            case RR * DD: rel_emb = (const float*)p; break;
            case 2 * DD:
                if (c256 == 0) e_attn = (const float*)p; else r_attn = (const float*)p;
                c256++;
                break;
            case F3 * F3:
                if (cgate == 0) e_gate = (const float*)p; else r_gate = (const float*)p;
                cgate++;
                break;
            case NP * F3:
                if (cprox == 0) e_proxy = (const float*)p; else r_proxy = (const float*)p;
                cprox++;
                break;
            case F3:
                if (cbias == 0) e_bias = (const float*)p; else r_bias = (const float*)p;
                cbias++;
                break;
            default: break; // scalars / mask: unused
        }
    }
    float* out = (float*)d_out;

    float* d_fA; cudaGetSymbolAddress((void**)&d_fA, g_fA);
    float* d_fB; cudaGetSymbolAddress((void**)&d_fB, g_fB);
    float* d_w;  cudaGetSymbolAddress((void**)&d_w, g_rel_w);

    const int ROWBLK = (NN + 7) / 8;  // warp-per-row, 8 warps/block

    // Prep
    prep_rel_kernel<<<(RR + 7) / 8, 256>>>(rel_emb, e_attn, r_attn);
    prep_proxy_kernel<<<16, 256>>>(e_proxy, r_proxy);

    // CSR build (3 adjacencies)
    zero_cnt_kernel<<<256, 256>>>();
    count_kernel<<<(TT + 255) / 256, 256>>>(ent_adj, rel_adj, adj_list);
    scan_local_kernel<<<dim3(NBLK, 3), 1024>>>();
    scan_bsum_kernel<<<1, 32>>>();
    scan_add_kernel<<<dim3(NBLK, 3), 1024>>>();
    fill_kernel<<<(TT + 255) / 256, 256>>>(ent_adj, rel_adj, adj_list, r_index, r_val);

    // ---------------- Edge phase: Encoder E then R ----------------
    avg_kernel<<<ROWBLK, 256>>>(0, ent_emb, d_fA, out + 0);
    nr_layer_kernel<<<ROWBLK, 256>>>(d_fA, d_fB, out + 128, d_w + 0 * RR);
    nr_layer_kernel<<<ROWBLK, 256>>>(d_fB, d_fA, out + 256, d_w + 1 * RR);

    avg_kernel<<<ROWBLK, 256>>>(1, rel_emb, d_fA, out + 384);
    nr_layer_kernel<<<ROWBLK, 256>>>(d_fA, d_fB, out + 384 + 128, d_w + 2 * RR);
    nr_layer_kernel<<<ROWBLK, 256>>>(d_fB, d_fA, out + 384 + 256, d_w + 3 * RR);

    // ---------------- Epilogue: both encoders in single launches ----------------
    epi1_kernel<<<dim3(ROWBLK, 2), 256>>>(out, e_proxy, r_proxy);
    gemm_gate_kernel<<<dim3(F3 / BN, (NN + BM - 1) / BM, 2), 256>>>(
        out, e_gate, r_gate, e_bias, r_bias);
}